// round 5
// baseline (speedup 1.0000x reference)
#include <cuda_runtime.h>
#include <math.h>

#define KSZ   1024
#define WNUM  1023
#define BNUM  2
#define NDL   16
#define TPB   256
#define TOTAL_FLOATS 33521664u   // 16 * 2 * 1023 * 1024 real-part floats

__device__ __forceinline__ float2 c_add(float2 a, float2 b) { return make_float2(a.x + b.x, a.y + b.y); }
__device__ __forceinline__ float2 c_sub(float2 a, float2 b) { return make_float2(a.x - b.x, a.y - b.y); }
__device__ __forceinline__ float2 c_mul(float2 a, float2 b) {
    return make_float2(fmaf(a.x, b.x, -a.y * b.y), fmaf(a.x, b.y, a.y * b.x));
}
#define SMSZ 1280
__device__ __forceinline__ int S(int i) {            // skew + hard clamp
    int v = i + (i >> 2);
    return v < 0 ? 0 : (v > SMSZ - 1 ? SMSZ - 1 : v);
}
__device__ __forceinline__ int clampi(int v, int lo, int hi) {
    return v < lo ? lo : (v > hi ? hi : v);
}

// ---------------------------------------------------------------------------
// One CTA per (b, w) window; 16 dechirped FFTs per CTA.
// Radix-4 Stockham autosort, forward FFT. Output = REAL PART only (float32).
// ---------------------------------------------------------------------------
__global__ void __launch_bounds__(TPB) stft_kernel(const float* __restrict__ x,
                                                   const float* __restrict__ dlnf,
                                                   float* __restrict__ out,
                                                   unsigned int x_n,
                                                   unsigned int dlnf_n,
                                                   unsigned int cap) {
    __shared__ float  wbuf[KSZ];
    __shared__ float2 bufA[SMSZ];
    __shared__ float2 bufB[SMSZ];
    __shared__ float2 tw[768];                // tw[r] = e^{-2pi i r/1024}
    __shared__ float  s_em1[NDL];
    __shared__ float  s_invb[NDL];
    __shared__ int    s_safe[NDL];

    const int tid = threadIdx.x;
    const int bw  = clampi(blockIdx.x, 0, BNUM * WNUM - 1);
    const int b   = bw / WNUM;
    const int w   = bw - b * WNUM;
    const unsigned int xbase = (unsigned int)b * 524288u + (unsigned int)w * 512u;

    // Per-d scalars (correctly-rounded f32 exp via double; fast-math-proof)
    if (tid < NDL) {
        const float beta = (tid < (int)dlnf_n) ? 2.0f * dlnf[tid] : 0.0f;
        const int safe = fabsf(beta) < 1e-8f;
        s_safe[tid] = safe;
        s_em1[tid]  = (float)exp((double)beta) - 1.0f;
        s_invb[tid] = safe ? 0.0f : 2.0f / beta;
    }

    // Window load (hann) + chirp held in registers (same for every d)
    float2 ch[4];
#pragma unroll
    for (int q = 0; q < 4; q++) {
        const int k = tid + TPB * q;
        const unsigned int gi = xbase + (unsigned int)k;
        const float xv = (gi < x_n) ? x[gi] : 0.0f;
        const float hann = 0.5f * (1.0f - __cosf(6.283185307179586f * (float)k * (1.0f / 1024.0f)));
        wbuf[k] = xv * hann;
        const float t = fmaf(2.0f * (1.0f / 1023.0f), (float)k, -1.0f);
        float s, c;
        __sincosf(0.5f * t * t, &s, &c);      // A = 0.5
        ch[q] = make_float2(c, -s);           // exp(-i*A*t^2)
    }
#pragma unroll
    for (int q = 0; q < 3; q++) {
        const int r = tid + TPB * q;
        float s, c;
        __sincosf(-6.283185307179586f * (float)r * (1.0f / 1024.0f), &s, &c);
        tw[r] = make_float2(c, s);
    }
    __syncthreads();

    for (int d = 0; d < NDL; d++) {
        const float em1  = s_em1[d];
        const float invb = s_invb[d];
        const int   safe = s_safe[d];

        // --- inline warp-resample + chirp into registers ---
        float2 v0, v1, v2, v3;
        {
            float2 vv[4];
#pragma unroll
            for (int q = 0; q < 4; q++) {
                const int k = tid + TPB * q;
                const float kf = (float)k;
                float t;
                if (safe) {
                    t = -1.0f + kf * (2.0f / 1023.0f);
                } else {
                    const float tau = kf * (1.0f / 1023.0f);
                    const float L = log1pf(tau * em1);
                    t = invb * L - 1.0f;
                }
                const float idxf = (t + 1.0f) * 0.5f * 1023.0f;
                const int lo = clampi((int)idxf, 0, 1022);
                const float frac = idxf - (float)lo;
                const float vlo = wbuf[lo];
                const float vhi = wbuf[lo + 1];
                const float val = vlo * (1.0f - frac) + vhi * frac;  // reference form
                vv[q] = make_float2(val * ch[q].x, val * ch[q].y);
            }
            v0 = vv[0]; v1 = vv[1]; v2 = vv[2]; v3 = vv[3];
        }

        // --- stage Ns=1: butterfly; scatter to bufA[4j+r] ---
        {
            const float2 t0 = c_add(v0, v2), t1 = c_sub(v0, v2), t2 = c_add(v1, v3);
            const float2 bd = c_sub(v1, v3);
            const float2 t3 = make_float2(bd.y, -bd.x);        // -i*(v1-v3)
            const int base = 4 * tid;
            bufA[S(base)]     = c_add(t0, t2);
            bufA[S(base + 1)] = c_add(t1, t3);
            bufA[S(base + 2)] = c_sub(t0, t2);
            bufA[S(base + 3)] = c_sub(t1, t3);
        }

        // --- stages Ns = 4, 16, 64 ---
        float2* src = bufA;
        float2* dst = bufB;
#pragma unroll
        for (int s = 1; s <= 3; s++) {
            __syncthreads();
            const int Ns = 1 << (2 * s);
            const int f  = 256 >> (2 * s);      // 1024/(4*Ns)
            const int p  = tid & (Ns - 1);
            const float2 a0 = src[S(tid)];
            const float2 a1 = c_mul(src[S(tid + 256)], tw[clampi(p * f, 0, 767)]);
            const float2 a2 = c_mul(src[S(tid + 512)], tw[clampi(2 * p * f, 0, 767)]);
            const float2 a3 = c_mul(src[S(tid + 768)], tw[clampi(3 * p * f, 0, 767)]);
            const float2 t0 = c_add(a0, a2), t1 = c_sub(a0, a2), t2 = c_add(a1, a3);
            const float2 bd = c_sub(a1, a3);
            const float2 t3 = make_float2(bd.y, -bd.x);
            const int idxD = ((tid - p) << 2) + p;   // (tid/Ns)*4Ns + p
            dst[S(idxD)]          = c_add(t0, t2);
            dst[S(idxD + Ns)]     = c_add(t1, t3);
            dst[S(idxD + 2 * Ns)] = c_sub(t0, t2);
            dst[S(idxD + 3 * Ns)] = c_sub(t1, t3);
            float2* tmp = src; src = dst; dst = tmp;
        }
        __syncthreads();

        // --- final stage Ns=256: REAL PART ONLY to global (float32) ---
        {
            const float2 a0 = src[S(tid)];
            const float2 a1 = c_mul(src[S(tid + 256)], tw[clampi(tid, 0, 767)]);
            const float2 a2 = c_mul(src[S(tid + 512)], tw[clampi(2 * tid, 0, 767)]);
            const float2 a3 = c_mul(src[S(tid + 768)], tw[clampi(3 * tid, 0, 767)]);
            const float2 t0 = c_add(a0, a2), t1 = c_sub(a0, a2), t2 = c_add(a1, a3);
            const float2 bd = c_sub(a1, a3);
            const float2 t3 = make_float2(bd.y, -bd.x);
            const unsigned int base = ((unsigned int)d * (BNUM * WNUM) + (unsigned int)bw) * KSZ
                                      + (unsigned int)tid;
            const float r0 = t0.x + t2.x;   // Re(V0)
            const float r1 = t1.x + t3.x;   // Re(V1)
            const float r2 = t0.x - t2.x;   // Re(V2)
            const float r3 = t1.x - t3.x;   // Re(V3)
            if (base +   0u < cap) out[base +   0u] = r0;
            if (base + 256u < cap) out[base + 256u] = r1;
            if (base + 512u < cap) out[base + 512u] = r2;
            if (base + 768u < cap) out[base + 768u] = r3;
        }
        __syncthreads();
    }
}

// ---------------------------------------------------------------------------
extern "C" void kernel_launch(void* const* d_in, const int* in_sizes, int n_in,
                              void* d_out, int out_size) {
    if (!d_in || !in_sizes || !d_out || n_in < 1) return;

    const float* x = nullptr;    long long xn = -1;
    const float* dl = nullptr;   long long dn = 0;
    for (int i = 0; i < n_in; i++) {
        if (!d_in[i]) continue;
        if ((long long)in_sizes[i] > xn) { xn = in_sizes[i]; x = (const float*)d_in[i]; }
    }
    for (int i = 0; i < n_in; i++) {
        if (!d_in[i] || (const float*)d_in[i] == x) continue;
        dl = (const float*)d_in[i]; dn = in_sizes[i];
    }
    if (!x || xn <= 0) return;
    if (!dl) { dl = x; dn = 0; }

    // Output is real-part float32: cap at out_size floats (and at the true total).
    long long cap = (long long)out_size;
    if (cap > (long long)TOTAL_FLOATS) cap = TOTAL_FLOATS;
    if (cap < 0) cap = 0;

    stft_kernel<<<BNUM * WNUM, TPB>>>(x, dl, (float*)d_out,
                                      (unsigned int)xn, (unsigned int)dn,
                                      (unsigned int)cap);
}

// round 6
// speedup vs baseline: 2.3670x; 2.3670x over previous
#include <cuda_runtime.h>
#include <math.h>

#define KSZ   1024
#define WNUM  1023
#define BNUM  2
#define NDL   16
#define TPB   256
#define TOTAL_FLOATS 33521664u   // 16 * 2 * 1023 * 1024 real-part floats

__device__ float2 g_lofrac[NDL * KSZ];  // (float)lo, frac
__device__ float2 g_tw[KSZ];            // e^{-2pi i r/1024}
__device__ float2 g_chirp[KSZ];         // exp(-i*0.5*t^2), t=linspace(-1,1,K)
__device__ float  g_hann[KSZ];

__device__ __forceinline__ float2 c_add(float2 a, float2 b) { return make_float2(a.x + b.x, a.y + b.y); }
__device__ __forceinline__ float2 c_sub(float2 a, float2 b) { return make_float2(a.x - b.x, a.y - b.y); }
__device__ __forceinline__ float2 c_mul(float2 a, float2 b) {
    return make_float2(fmaf(a.x, b.x, -a.y * b.y), fmaf(a.x, b.y, a.y * b.x));
}
__device__ __forceinline__ int clampi(int v, int lo, int hi) {
    return v < lo ? lo : (v > hi ? hi : v);
}
// Skew for 1024-float2 exchange buffers (verified conflict-free on all patterns)
#define BUFSZ 1088
__device__ __forceinline__ int S16(int i) { return i + (i >> 4); }

// radix-4 butterfly in place (forward, w4 = -i)
__device__ __forceinline__ void r4(float2& x0, float2& x1, float2& x2, float2& x3) {
    float2 t0 = c_add(x0, x2), t1 = c_sub(x0, x2), t2 = c_add(x1, x3);
    float2 bd = c_sub(x1, x3);
    float2 t3 = make_float2(bd.y, -bd.x);
    x0 = c_add(t0, t2); x1 = c_add(t1, t3); x2 = c_sub(t0, t2); x3 = c_sub(t1, t3);
}

// 16-point forward DFT in registers. Input X[r] natural order.
// OUTPUT PERMUTED: Y[k1 + 4*k2] lands in slot X[4*k1 + k2].
__device__ __forceinline__ void dft16(float2 X[16]) {
    r4(X[0], X[4], X[8],  X[12]);
    r4(X[1], X[5], X[9],  X[13]);
    r4(X[2], X[6], X[10], X[14]);
    r4(X[3], X[7], X[11], X[15]);
    const float C1 = 0.9238795325112867f, S1 = 0.3826834323650898f, R2 = 0.7071067811865476f;
    X[5]  = c_mul(X[5],  make_float2( C1, -S1));  // w16^1
    X[9]  = c_mul(X[9],  make_float2( R2, -R2));  // w16^2
    X[13] = c_mul(X[13], make_float2( S1, -C1));  // w16^3
    X[6]  = c_mul(X[6],  make_float2( R2, -R2));  // w16^2
    X[10] = c_mul(X[10], make_float2(0.f, -1.f)); // w16^4
    X[14] = c_mul(X[14], make_float2(-R2, -R2));  // w16^6
    X[7]  = c_mul(X[7],  make_float2( S1, -C1));  // w16^3
    X[11] = c_mul(X[11], make_float2(-R2, -R2));  // w16^6
    X[15] = c_mul(X[15], make_float2(-C1,  S1));  // w16^9
    r4(X[0],  X[1],  X[2],  X[3]);
    r4(X[4],  X[5],  X[6],  X[7]);
    r4(X[8],  X[9],  X[10], X[11]);
    r4(X[12], X[13], X[14], X[15]);
}

// ---------------------------------------------------------------------------
// Prep: tables. Blocks 0..15 -> lofrac (mirrors reference f32 math exactly);
// block 16 -> tw / chirp / hann (double precision, more accurate than ref).
// ---------------------------------------------------------------------------
__global__ void prep_kernel(const float* __restrict__ dlnf, unsigned int dlnf_n) {
    const int k = threadIdx.x;
    const int bid = blockIdx.x;
    if (bid < NDL) {
        const float beta = (bid < (int)dlnf_n) ? 2.0f * dlnf[bid] : 0.0f;
        float tsrc;
        if (fabsf(beta) < 1e-8f) {
            tsrc = -1.0f + (float)k * (2.0f / 1023.0f);
        } else {
            const float em1 = (float)exp((double)beta) - 1.0f;   // fast-math-proof
            const float tau = (float)k * (1.0f / 1023.0f);
            tsrc = (2.0f / beta) * log1pf(tau * em1) - 1.0f;
        }
        const float idx = (tsrc + 1.0f) * 0.5f * 1023.0f;
        int lo = clampi((int)idx, 0, 1022);
        g_lofrac[bid * KSZ + k] = make_float2((float)lo, idx - (float)lo);
    } else {
        const double kk = (double)k;
        const double ang = -6.283185307179586476925287 * kk / 1024.0;
        g_tw[k] = make_float2((float)cos(ang), (float)sin(ang));
        const double t = -1.0 + 2.0 * kk / 1023.0;
        const double ph = -0.5 * t * t;                           // A = 0.5
        g_chirp[k] = make_float2((float)cos(ph), (float)sin(ph));
        g_hann[k] = (float)(0.5 * (1.0 - cos(6.283185307179586476925287 * kk / 1024.0)));
    }
}

// ---------------------------------------------------------------------------
// Main: one CTA per (b, w). 256 threads = 4 groups of 64; each group runs one
// 1024-pt FFT (16 pts/thread) over d = g, g+4, g+8, g+12.
// Stockham 16 x 16 x 4: regs -> smem -> regs -> smem -> regs -> global(Re).
// ---------------------------------------------------------------------------
__global__ void __launch_bounds__(TPB) stft_kernel(const float* __restrict__ x,
                                                   float* __restrict__ out,
                                                   unsigned int x_n,
                                                   unsigned int cap) {
    extern __shared__ float sm[];
    float*  wbuf = sm;                           // 1024 floats
    float2* bufs = (float2*)(sm + KSZ);          // 8 * BUFSZ float2

    const int tid = threadIdx.x;
    const int g   = tid >> 6;                    // group 0..3
    const int j   = tid & 63;                    // lane within group
    float2* bufA = bufs + (size_t)(2 * g) * BUFSZ;
    float2* bufB = bufs + (size_t)(2 * g + 1) * BUFSZ;

    const int bw = blockIdx.x;
    const int b  = bw / WNUM;
    const int w  = bw - b * WNUM;
    const unsigned int xbase = (unsigned int)b * 524288u + (unsigned int)w * 512u;

    // Window (hann) into smem — zero transcendentals
#pragma unroll
    for (int q = 0; q < 4; q++) {
        const int k = tid + TPB * q;
        const unsigned int gi = xbase + (unsigned int)k;
        const float xv = (gi < x_n) ? x[gi] : 0.0f;
        wbuf[k] = xv * g_hann[k];
    }

    // Per-thread constants (L1-resident LDGs, reused over all 4 FFTs)
    float2 ch[16];
#pragma unroll
    for (int r = 0; r < 16; r++) ch[r] = g_chirp[j + 64 * r];
    const int p = j & 15;
    const float2 w2base = g_tw[4 * p];           // w256^p = w1024^{4p}
    float2 w3base[4];
#pragma unroll
    for (int q = 0; q < 4; q++) w3base[q] = g_tw[j + 64 * q];   // w1024^{jj}
    __syncthreads();

#pragma unroll 1
    for (int it = 0; it < 4; it++) {
        const int d = g + 4 * it;
        const float2* lf = g_lofrac + d * KSZ;

        // --- resample + chirp into registers ---
        float2 X[16];
#pragma unroll
        for (int r = 0; r < 16; r++) {
            const float2 L = lf[j + 64 * r];
            const int lo = (int)L.x;             // pre-clamped in prep
            const float vlo = wbuf[lo];
            const float vhi = wbuf[lo + 1];
            const float val = vlo * (1.0f - L.y) + vhi * L.y;   // reference form
            X[r] = make_float2(val * ch[r].x, val * ch[r].y);
        }

        // --- iter1: Ns=1, R=16 (no twiddle); write bufA[16j + r'] ---
        dft16(X);
#pragma unroll
        for (int k1 = 0; k1 < 4; k1++)
#pragma unroll
            for (int k2 = 0; k2 < 4; k2++)
                bufA[S16(16 * j + (k1 + 4 * k2))] = X[4 * k1 + k2];
        __syncthreads();

        // --- iter2: Ns=16, R=16; twiddle w1024^{4 p r}; write idxD + 16 r' ---
#pragma unroll
        for (int r = 0; r < 16; r++) X[r] = bufA[S16(j + 64 * r)];
        {
            float2 wc = w2base;
#pragma unroll
            for (int r = 1; r < 16; r++) {
                X[r] = c_mul(X[r], wc);
                if (r < 15) wc = c_mul(wc, w2base);
            }
        }
        dft16(X);
        const int idxD = ((j >> 4) << 8) + p;    // (j/16)*256 + p
#pragma unroll
        for (int k1 = 0; k1 < 4; k1++)
#pragma unroll
            for (int k2 = 0; k2 < 4; k2++)
                bufB[S16(idxD + 16 * (k1 + 4 * k2))] = X[4 * k1 + k2];
        __syncthreads();

        // --- iter3: Ns=256, R=4; twiddle w1024^{jj r}; Re -> global ---
        const unsigned int obase = ((unsigned int)d * (BNUM * WNUM) + (unsigned int)bw) * KSZ;
#pragma unroll
        for (int q = 0; q < 4; q++) {
            const int jj = j + 64 * q;
            float2 a0 = bufB[S16(jj)];
            float2 a1 = bufB[S16(jj + 256)];
            float2 a2 = bufB[S16(jj + 512)];
            float2 a3 = bufB[S16(jj + 768)];
            const float2 w1 = w3base[q];
            const float2 w2 = c_mul(w1, w1);
            const float2 w3 = c_mul(w2, w1);
            a1 = c_mul(a1, w1); a2 = c_mul(a2, w2); a3 = c_mul(a3, w3);
            const float2 t0 = c_add(a0, a2), t1 = c_sub(a0, a2), t2 = c_add(a1, a3);
            const float2 bd = c_sub(a1, a3);
            const float2 t3 = make_float2(bd.y, -bd.x);
            const unsigned int o = obase + (unsigned int)jj;
            if (o +   0u < cap) out[o +   0u] = t0.x + t2.x;
            if (o + 256u < cap) out[o + 256u] = t1.x + t3.x;
            if (o + 512u < cap) out[o + 512u] = t0.x - t2.x;
            if (o + 768u < cap) out[o + 768u] = t1.x - t3.x;
        }
        // iter3 read bufB; next iter1 writes bufA; next bufB write is after
        // the next __syncthreads() -> no extra barrier needed here.
    }
}

#define SMEM_BYTES (KSZ * 4 + 8 * BUFSZ * 8)   // 4096 + 69632 = 73728

// ---------------------------------------------------------------------------
extern "C" void kernel_launch(void* const* d_in, const int* in_sizes, int n_in,
                              void* d_out, int out_size) {
    if (!d_in || !in_sizes || !d_out || n_in < 1) return;

    const float* x = nullptr;   long long xn = -1;
    const float* dl = nullptr;  long long dn = 0;
    for (int i = 0; i < n_in; i++) {
        if (!d_in[i]) continue;
        if ((long long)in_sizes[i] > xn) { xn = in_sizes[i]; x = (const float*)d_in[i]; }
    }
    for (int i = 0; i < n_in; i++) {
        if (!d_in[i] || (const float*)d_in[i] == x) continue;
        dl = (const float*)d_in[i]; dn = in_sizes[i];
    }
    if (!x || xn <= 0) return;
    if (!dl) { dl = x; dn = 0; }

    long long cap = (long long)out_size;
    if (cap > (long long)TOTAL_FLOATS) cap = TOTAL_FLOATS;
    if (cap < 0) cap = 0;

    cudaFuncSetAttribute(stft_kernel, cudaFuncAttributeMaxDynamicSharedMemorySize, SMEM_BYTES);

    prep_kernel<<<NDL + 1, KSZ>>>(dl, (unsigned int)dn);
    stft_kernel<<<BNUM * WNUM, TPB, SMEM_BYTES>>>(x, (float*)d_out,
                                                  (unsigned int)xn, (unsigned int)cap);
}

// round 7
// speedup vs baseline: 3.5604x; 1.5042x over previous
#include <cuda_runtime.h>
#include <math.h>

#define KSZ   1024
#define WNUM  1023
#define BNUM  2
#define NDL   16
#define TPB   256
#define TOTAL_FLOATS 33521664u   // 16 * 2 * 1023 * 1024 real-part floats

__device__ float2 g_lofrac[NDL * KSZ];  // (float)lo, frac
__device__ float2 g_tw[KSZ];            // e^{-2pi i r/1024}
__device__ float2 g_chirp[KSZ];         // exp(-i*0.5*t^2), t=linspace(-1,1,K)
__device__ float2 g_hpair[KSZ];         // (hann[k], hann[k+1])

__device__ __forceinline__ float2 c_add(float2 a, float2 b) { return make_float2(a.x + b.x, a.y + b.y); }
__device__ __forceinline__ float2 c_sub(float2 a, float2 b) { return make_float2(a.x - b.x, a.y - b.y); }
__device__ __forceinline__ float2 c_mul(float2 a, float2 b) {
    return make_float2(fmaf(a.x, b.x, -a.y * b.y), fmaf(a.x, b.y, a.y * b.x));
}
__device__ __forceinline__ int clampi(int v, int lo, int hi) {
    return v < lo ? lo : (v > hi ? hi : v);
}
// dft16 slot->frequency map (involution): slot s holds frequency F16(s)
__device__ __forceinline__ constexpr int F16(int s) { return (s >> 2) + 4 * (s & 3); }

// radix-4 butterfly in place (forward, w4 = -i)
__device__ __forceinline__ void r4(float2& x0, float2& x1, float2& x2, float2& x3) {
    float2 t0 = c_add(x0, x2), t1 = c_sub(x0, x2), t2 = c_add(x1, x3);
    float2 bd = c_sub(x1, x3);
    float2 t3 = make_float2(bd.y, -bd.x);
    x0 = c_add(t0, t2); x1 = c_add(t1, t3); x2 = c_sub(t0, t2); x3 = c_sub(t1, t3);
}

// 16-point forward DFT in registers; output permuted: Y[F16(s)] lands in slot s.
__device__ __forceinline__ void dft16(float2 X[16]) {
    r4(X[0], X[4], X[8],  X[12]);
    r4(X[1], X[5], X[9],  X[13]);
    r4(X[2], X[6], X[10], X[14]);
    r4(X[3], X[7], X[11], X[15]);
    const float C1 = 0.9238795325112867f, S1 = 0.3826834323650898f, R2 = 0.7071067811865476f;
    X[5]  = c_mul(X[5],  make_float2( C1, -S1));
    X[9]  = c_mul(X[9],  make_float2( R2, -R2));
    X[13] = c_mul(X[13], make_float2( S1, -C1));
    X[6]  = c_mul(X[6],  make_float2( R2, -R2));
    X[10] = c_mul(X[10], make_float2(0.f, -1.f));
    X[14] = c_mul(X[14], make_float2(-R2, -R2));
    X[7]  = c_mul(X[7],  make_float2( S1, -C1));
    X[11] = c_mul(X[11], make_float2(-R2, -R2));
    X[15] = c_mul(X[15], make_float2(-C1,  S1));
    r4(X[0],  X[1],  X[2],  X[3]);
    r4(X[4],  X[5],  X[6],  X[7]);
    r4(X[8],  X[9],  X[10], X[11]);
    r4(X[12], X[13], X[14], X[15]);
}

// dft32 via radix-2 + two dft16: on return e[s]=Y[F16(s)], o[s]=Y[F16(s)+16].
__device__ __forceinline__ void dft32(float2 e[16], float2 o[16]) {
    dft16(e);
    dft16(o);
    // w32^f = (cos(pi f/16), -sin(pi f/16))
    const float2 W32[16] = {
        { 1.0000000000f,  0.0000000000f}, { 0.9807852804f, -0.1950903220f},
        { 0.9238795325f, -0.3826834324f}, { 0.8314696123f, -0.5555702330f},
        { 0.7071067812f, -0.7071067812f}, { 0.5555702330f, -0.8314696123f},
        { 0.3826834324f, -0.9238795325f}, { 0.1950903220f, -0.9807852804f},
        { 0.0000000000f, -1.0000000000f}, {-0.1950903220f, -0.9807852804f},
        {-0.3826834324f, -0.9238795325f}, {-0.5555702330f, -0.8314696123f},
        {-0.7071067812f, -0.7071067812f}, {-0.8314696123f, -0.5555702330f},
        {-0.9238795325f, -0.3826834324f}, {-0.9807852804f, -0.1950903220f}};
#pragma unroll
    for (int s = 0; s < 16; s++) {
        const int f = F16(s);
        const float2 t = c_mul(o[s], W32[f]);
        const float2 lo2 = c_sub(e[s], t);
        e[s] = c_add(e[s], t);     // Y[f]
        o[s] = lo2;                // Y[f+16]
    }
}

// ---------------------------------------------------------------------------
// Prep: blocks 0..15 -> lofrac (mirrors reference f32 math); block 16 -> tables
// (fast f32 trig; double kept only for the 16 exp(beta) scalars).
// ---------------------------------------------------------------------------
__global__ void prep_kernel(const float* __restrict__ dlnf, unsigned int dlnf_n) {
    const int k = threadIdx.x;
    const int bid = blockIdx.x;
    if (bid < NDL) {
        const float beta = (bid < (int)dlnf_n) ? 2.0f * dlnf[bid] : 0.0f;
        float tsrc;
        if (fabsf(beta) < 1e-8f) {
            tsrc = -1.0f + (float)k * (2.0f / 1023.0f);
        } else {
            const float em1 = (float)exp((double)beta) - 1.0f;   // fast-math-proof
            const float tau = (float)k * (1.0f / 1023.0f);
            tsrc = (2.0f / beta) * log1pf(tau * em1) - 1.0f;
        }
        const float idx = (tsrc + 1.0f) * 0.5f * 1023.0f;
        int lo = clampi((int)idx, 0, 1022);
        g_lofrac[bid * KSZ + k] = make_float2((float)lo, idx - (float)lo);
    } else {
        const float kf = (float)k;
        float s, c;
        __sincosf(-6.283185307179586f * kf * (1.0f / 1024.0f), &s, &c);
        g_tw[k] = make_float2(c, s);
        const float t = fmaf(2.0f * (1.0f / 1023.0f), kf, -1.0f);
        __sincosf(-0.5f * t * t, &s, &c);
        g_chirp[k] = make_float2(c, s);
        const float h0 = 0.5f * (1.0f - __cosf(6.283185307179586f * kf * (1.0f / 1024.0f)));
        const float h1 = (k < KSZ - 1)
            ? 0.5f * (1.0f - __cosf(6.283185307179586f * (kf + 1.0f) * (1.0f / 1024.0f)))
            : 0.0f;   // hpair[1023].y never used (lo <= 1022)
        g_hpair[k] = make_float2(h0, h1);
    }
}

// ---------------------------------------------------------------------------
// Main: one CTA per (b, w); 8 warps; each warp = one 1024-pt FFT (32 pts/thr).
// Warp wid handles d = wid and wid + 8. Single smem transpose, no CTA barriers
// in the hot loop.
// ---------------------------------------------------------------------------
#define XCH_STRIDE 33
#define XCH_SZ     1056           // 32*33 float2 per warp
__global__ void __launch_bounds__(TPB, 2) stft_kernel(const float* __restrict__ x,
                                                      float* __restrict__ out,
                                                      unsigned int x_n,
                                                      unsigned int cap) {
    extern __shared__ float sm[];
    float2* wpair = (float2*)sm;                            // 1024 float2
    const int tid  = threadIdx.x;
    const int lane = tid & 31;
    const int wid  = tid >> 5;
    float2* xch = (float2*)sm + KSZ + (size_t)wid * XCH_SZ; // per-warp 8448B

    const int bw = blockIdx.x;
    const int b  = bw / WNUM;
    const int w  = bw - b * WNUM;
    const unsigned int xbase = (unsigned int)b * 524288u + (unsigned int)w * 512u;

    // Build windowed pair table: wpair[k] = (x[k]*h[k], x[k+1]*h[k+1])
#pragma unroll
    for (int q = 0; q < 4; q++) {
        const int k = tid + TPB * q;
        const unsigned int gi = xbase + (unsigned int)k;
        const float xv0 = (gi < x_n) ? x[gi] : 0.0f;
        const float xv1 = (gi + 1u < x_n) ? x[gi + 1u] : 0.0f;
        const float2 hp = g_hpair[k];
        wpair[k] = make_float2(xv0 * hp.x, xv1 * hp.y);
    }
    const float2 wbase = g_tw[lane];        // w1024^lane
    __syncthreads();

#pragma unroll 1
    for (int it = 0; it < 2; it++) {
        const int d = wid + 8 * it;
        const float2* lf = g_lofrac + d * KSZ;

        // --- step 1 inputs: resample + chirp; even/odd split over n2 ---
        float2 e[16], o[16];
#pragma unroll
        for (int j = 0; j < 16; j++) {
            {
                const int n = lane + 64 * j;            // n2 = 2j
                const float2 L = lf[n];
                const float2 wp = wpair[(int)L.x];
                const float val = wp.x * (1.0f - L.y) + wp.y * L.y;
                const float2 c = g_chirp[n];
                e[j] = make_float2(val * c.x, val * c.y);
            }
            {
                const int n = lane + 64 * j + 32;       // n2 = 2j+1
                const float2 L = lf[n];
                const float2 wp = wpair[(int)L.x];
                const float val = wp.x * (1.0f - L.y) + wp.y * L.y;
                const float2 c = g_chirp[n];
                o[j] = make_float2(val * c.x, val * c.y);
            }
        }

        // --- step 1: DFT32 over n2 (thread = n1 = lane) ---
        dft32(e, o);    // e[s] = A[F16(s)], o[s] = A[F16(s)+16]

        // --- step 2+3: twiddle w1024^{n1*k2} (iterated), transpose via smem ---
        __syncwarp();   // previous iteration's reads of xch complete
        {
            float2 wc = wbase;  // w1024^{lane * k2} for k2 = 1
#pragma unroll
            for (int k2 = 0; k2 < 32; k2++) {
                const int s = (k2 < 16) ? F16(k2) : F16(k2 - 16);
                float2 v = (k2 < 16) ? e[s] : o[s];
                if (k2 > 0) v = c_mul(v, wc);
                xch[lane * XCH_STRIDE + k2] = v;
                if (k2 > 0 && k2 < 31) wc = c_mul(wc, wbase);
            }
        }
        __syncwarp();

        // --- step 4: gather column (thread = k2 = lane), DFT32 over n1 ---
#pragma unroll
        for (int j = 0; j < 16; j++) {
            e[j] = xch[(2 * j)     * XCH_STRIDE + lane];
            o[j] = xch[(2 * j + 1) * XCH_STRIDE + lane];
        }
        dft32(e, o);    // e[s] = X[lane + 32*F16(s)], o[s] = X[lane + 32*(F16(s)+16)]

        // --- store Re only, coalesced ---
        const unsigned int obase = ((unsigned int)d * (BNUM * WNUM) + (unsigned int)bw) * KSZ
                                   + (unsigned int)lane;
#pragma unroll
        for (int s = 0; s < 16; s++) {
            const int f = F16(s);
            const unsigned int o1 = obase + 32u * (unsigned int)f;
            const unsigned int o2 = o1 + 512u;      // 32*(f+16)
            if (o1 < cap) out[o1] = e[s].x;
            if (o2 < cap) out[o2] = o[s].x;
        }
    }
}

#define SMEM_BYTES (KSZ * 8 + 8 * XCH_SZ * 8)   // 8192 + 67584 = 75776

// ---------------------------------------------------------------------------
extern "C" void kernel_launch(void* const* d_in, const int* in_sizes, int n_in,
                              void* d_out, int out_size) {
    if (!d_in || !in_sizes || !d_out || n_in < 1) return;

    const float* x = nullptr;   long long xn = -1;
    const float* dl = nullptr;  long long dn = 0;
    for (int i = 0; i < n_in; i++) {
        if (!d_in[i]) continue;
        if ((long long)in_sizes[i] > xn) { xn = in_sizes[i]; x = (const float*)d_in[i]; }
    }
    for (int i = 0; i < n_in; i++) {
        if (!d_in[i] || (const float*)d_in[i] == x) continue;
        dl = (const float*)d_in[i]; dn = in_sizes[i];
    }
    if (!x || xn <= 0) return;
    if (!dl) { dl = x; dn = 0; }

    long long cap = (long long)out_size;
    if (cap > (long long)TOTAL_FLOATS) cap = TOTAL_FLOATS;
    if (cap < 0) cap = 0;

    cudaFuncSetAttribute(stft_kernel, cudaFuncAttributeMaxDynamicSharedMemorySize, SMEM_BYTES);

    prep_kernel<<<NDL + 1, KSZ>>>(dl, (unsigned int)dn);
    stft_kernel<<<BNUM * WNUM, TPB, SMEM_BYTES>>>(x, (float*)d_out,
                                                  (unsigned int)xn, (unsigned int)cap);
}